// round 13
// baseline (speedup 1.0000x reference)
#include <cuda_runtime.h>
#include <cuda_bf16.h>
#include <mma.h>
#include <math.h>
#include <cstdint>

using namespace nvcuda;

// Problem constants
#define BB 2
#define SS 1024
#define DD 2048
#define FF 8192
#define EE 4
#define NT (BB*SS)            // 2048 tokens
#define WSZ ((size_t)EE*DD*FF)
#define HROWS ((size_t)EE*2048)

// ---------------- device scratch (no allocations allowed) ----------------
__device__ int   g_cnt[EE];
__device__ int   g_tok[EE][NT];
__device__ float g_gate[EE][NT];
// pre-split bf16 hi/lo planes
__device__ __nv_bfloat16 g_Wg_hi[WSZ], g_Wg_lo[WSZ];
__device__ __nv_bfloat16 g_Wu_hi[WSZ], g_Wu_lo[WSZ];
__device__ __nv_bfloat16 g_Wd_hi[WSZ], g_Wd_lo[WSZ];
__device__ __nv_bfloat16 g_x_hi[(size_t)NT*DD], g_x_lo[(size_t)NT*DD];
__device__ __nv_bfloat16 g_Hh[HROWS*FF], g_Hl[HROWS*FF];

// ---------------- helpers ----------------
__device__ __forceinline__ uint32_t smem_u32(const void* p) {
    uint32_t a;
    asm("{ .reg .u64 t; cvta.to.shared.u64 t, %1; cvt.u32.u64 %0, t; }" : "=r"(a) : "l"(p));
    return a;
}
__device__ __forceinline__ void cpa16(uint32_t dst, const void* src) {
    asm volatile("{ .reg .u64 g; cvta.to.global.u64 g, %1; cp.async.cg.shared.global [%0], [g], 16; }"
                 :: "r"(dst), "l"(src) : "memory");
}
#define CPA_COMMIT() asm volatile("cp.async.commit_group;" ::: "memory")
#define CPA_WAIT1()  asm volatile("cp.async.wait_group 1;" ::: "memory")
#define CPA_WAIT0()  asm volatile("cp.async.wait_group 0;" ::: "memory")

// bulk copy with per-thread expect_tx on the stage mbarrier
__device__ __forceinline__ void bulk_cp(uint32_t mbar, uint32_t dst, const void* src, uint32_t bytes) {
    asm volatile(
        "{ .reg .u64 g; cvta.to.global.u64 g, %3;\n\t"
        "mbarrier.arrive.expect_tx.shared.b64 _, [%0], %1;\n\t"
        "cp.async.bulk.shared::cta.global.mbarrier::complete_tx::bytes [%2], [g], %1, [%0]; }"
        :: "r"(mbar), "r"(bytes), "r"(dst), "l"(src) : "memory");
}
#define MBARRIER_INIT(mbar, cnt) \
    asm volatile("mbarrier.init.shared.b64 [%0], %1;" :: "r"((uint32_t)(mbar)), "r"((uint32_t)(cnt)) : "memory")
#define FENCE_ASYNC_SHARED() asm volatile("fence.proxy.async.shared::cta;" ::: "memory")

__device__ __forceinline__ void mbar_wait_parity(uint32_t mbar, uint32_t parity) {
    uint32_t done;
    asm volatile(
        "{\n\t.reg .pred p;\n\t"
        "mbarrier.try_wait.parity.acquire.cta.shared::cta.b64 p, [%1], %2;\n\t"
        "selp.b32 %0, 1, 0, p;\n\t}"
        : "=r"(done) : "r"(mbar), "r"(parity) : "memory");
    if (!done) {
        asm volatile(
            "{\n\t.reg .pred P1;\n\t"
            "WL_%=:\n\t"
            "mbarrier.try_wait.parity.acquire.cta.shared::cta.b64 P1, [%0], %1, 0x989680;\n\t"
            "@P1 bra.uni WD_%=;\n\t"
            "bra.uni WL_%=;\n\t"
            "WD_%=:\n\t}"
            :: "r"(mbar), "r"(parity) : "memory");
    }
}

__device__ __forceinline__ void split1(float v, unsigned short& h, unsigned short& l) {
    __nv_bfloat16 hb = __float2bfloat16(v);
    h = __bfloat16_as_ushort(hb);
    l = __bfloat16_as_ushort(__float2bfloat16(v - __bfloat162float(hb)));
}
__device__ __forceinline__ unsigned int pk2(unsigned short a, unsigned short b) {
    return (unsigned int)a | ((unsigned int)b << 16);
}

// ---------------- init / split / router ----------------
__global__ void init_kernel(float* __restrict__ out, int n) {
    int i = blockIdx.x * blockDim.x + threadIdx.x;
    if (i < n) out[i] = 0.0f;
    if (i < EE) g_cnt[i] = 0;
}

__global__ void split_kernel(const float* __restrict__ src, __nv_bfloat16* __restrict__ hi,
                             __nv_bfloat16* __restrict__ lo, size_t n4) {
    size_t i = (size_t)blockIdx.x * blockDim.x + threadIdx.x;
    if (i >= n4) return;
    float4 v = *(const float4*)(src + i * 4);
    float a[4] = {v.x, v.y, v.z, v.w};
    unsigned short h[4], l[4];
    #pragma unroll
    for (int t = 0; t < 4; t++) split1(a[t], h[t], l[t]);
    *(uint2*)(hi + i * 4) = make_uint2(pk2(h[0], h[1]), pk2(h[2], h[3]));
    *(uint2*)(lo + i * 4) = make_uint2(pk2(l[0], l[1]), pk2(l[2], l[3]));
}

__global__ void router_kernel(const float* __restrict__ x, const float* __restrict__ Wr) {
    int gwarp = (blockIdx.x * blockDim.x + threadIdx.x) >> 5;
    int lane  = threadIdx.x & 31;
    if (gwarp >= NT) return;
    const float* xr = x + (size_t)gwarp * DD;
    float a0 = 0.f, a1 = 0.f, a2 = 0.f, a3 = 0.f;
    for (int d = lane; d < DD; d += 32) {
        float xv = xr[d];
        float4 w = *(const float4*)(Wr + (size_t)d * 4);
        a0 += xv * w.x; a1 += xv * w.y; a2 += xv * w.z; a3 += xv * w.w;
    }
    #pragma unroll
    for (int off = 16; off; off >>= 1) {
        a0 += __shfl_down_sync(0xffffffffu, a0, off);
        a1 += __shfl_down_sync(0xffffffffu, a1, off);
        a2 += __shfl_down_sync(0xffffffffu, a2, off);
        a3 += __shfl_down_sync(0xffffffffu, a3, off);
    }
    if (lane == 0) {
        float l[4] = {a0, a1, a2, a3};
        float m = fmaxf(fmaxf(l[0], l[1]), fmaxf(l[2], l[3]));
        float p[4], s = 0.f;
        #pragma unroll
        for (int e = 0; e < 4; e++) { p[e] = expf(l[e] - m); s += p[e]; }
        int i0 = 0; float b0 = p[0];
        #pragma unroll
        for (int e = 1; e < 4; e++) if (p[e] > b0) { b0 = p[e]; i0 = e; }
        int i1 = -1; float b1 = -1.f;
        #pragma unroll
        for (int e = 0; e < 4; e++) if (e != i0 && p[e] > b1) { b1 = p[e]; i1 = e; }
        float inv = 1.f / s;
        int pos0 = atomicAdd(&g_cnt[i0], 1);
        g_tok[i0][pos0] = gwarp; g_gate[i0][pos0] = b0 * inv;
        int pos1 = atomicAdd(&g_cnt[i1], 1);
        g_tok[i1][pos1] = gwarp; g_gate[i1][pos1] = b1 * inv;
    }
}

// ================= smem layout =================
// data starts at +64 (mbarriers at +0,+8)
#define DATA0   64
// gateup: A [128][40] x2, B [32][136] x4
#define GU_AB   10240
#define GU_BB   8704
#define GU_STG  (2*GU_AB + 4*GU_BB)    // 55296
#define GU_SMEM (DATA0 + 2*GU_STG)     // 110656
// down: A [128][40] x2, B [32][264] x2 (BN=256)
#define DN_AB   10240
#define DN_BB   16896
#define DN_STG  (2*DN_AB + 2*DN_BB)    // 54272
#define DN_SMEM (DATA0 + 2*DN_STG)     // 108608

typedef wmma::fragment<wmma::matrix_a, 16, 16, 16, __nv_bfloat16, wmma::row_major> FragA;
typedef wmma::fragment<wmma::matrix_b, 16, 16, 16, __nv_bfloat16, wmma::row_major> FragB;
typedef wmma::fragment<wmma::accumulator, 16, 16, 16, float> FragC;

// ================= GEMM1: gate+up (bf16x3 HMMA) + SiLU*mul -> H hi/lo =================
// BM=128, BN=128+128 (G,U), BK=32, 512 threads = 16 warps: 2m x 2mat x 4n, warp 64x32.
// Weights via cp.async.bulk (mbarrier), A(x gather) via LDGSTS.
__global__ __launch_bounds__(512, 1) void gemm_gateup()
{
    const int e  = blockIdx.x >> 4;
    const int rb = blockIdx.x & 15;
    const int ne = g_cnt[e];
    if (rb * 128 >= ne) return;
    const int nb = blockIdx.y;

    extern __shared__ char smem[];
    const uint32_t sb = smem_u32(smem);
    const int tid  = threadIdx.x;
    const int warp = tid >> 5;
    const int wm   = warp >> 3;
    const int mat  = (warp >> 2) & 1;
    const int wn   = warp & 3;

    if (tid == 0) {
        MBARRIER_INIT(sb + 0, 128);
        MBARRIER_INIT(sb + 8, 128);
        FENCE_ASYNC_SHARED();
    }
    __syncthreads();

    // A loader: 128 rows x 4 chunks(16B) -> 512 slots, hi+lo
    const int arow = tid >> 2, achk = (tid & 3) * 8;
    const int tok  = g_tok[e][min(rb * 128 + arow, ne - 1)];
    const __nv_bfloat16* sAh = g_x_hi + (size_t)tok * DD + achk;
    const __nv_bfloat16* sAl = g_x_lo + (size_t)tok * DD + achk;
    const uint32_t dA = sb + DATA0 + (uint32_t)arow * 80 + achk * 2;

    // B bulk loader: threads 0..127, plane = tid>>5 (Gh,Gl,Uh,Ul), row = tid&31
    const __nv_bfloat16* bsrc = nullptr;
    uint32_t bdst = 0;
    if (tid < 128) {
        const int plane = tid >> 5, row = tid & 31;
        const __nv_bfloat16* pb =
            (plane == 0) ? g_Wg_hi : (plane == 1) ? g_Wg_lo : (plane == 2) ? g_Wu_hi : g_Wu_lo;
        bsrc = pb + (size_t)e * DD * FF + (size_t)row * FF + (size_t)nb * 128;
        bdst = sb + DATA0 + 2 * GU_AB + plane * GU_BB + row * 272;
    }

    #define GU_LOAD_A(st, k) do { \
        uint32_t o = (uint32_t)(st) * GU_STG; \
        cpa16(dA + o,         sAh + (k)); \
        cpa16(dA + o + GU_AB, sAl + (k)); \
    } while (0)
    #define GU_LOAD_B(st, k) do { \
        if (tid < 128) bulk_cp(sb + (st) * 8, bdst + (uint32_t)(st) * GU_STG, bsrc + (size_t)(k) * FF, 256); \
    } while (0)

    FragC c[4][2];
    #pragma unroll
    for (int m = 0; m < 4; m++)
        #pragma unroll
        for (int n = 0; n < 2; n++) wmma::fill_fragment(c[m][n], 0.f);

    GU_LOAD_A(0, 0);  CPA_COMMIT();
    GU_LOAD_A(1, 32); CPA_COMMIT();
    GU_LOAD_B(0, 0);
    GU_LOAD_B(1, 32);

    const int NS = DD / 32;   // 64
    #pragma unroll 1
    for (int s = 0; s < NS; s++) {
        if (s + 1 < NS) CPA_WAIT1(); else CPA_WAIT0();
        mbar_wait_parity(sb + (s & 1) * 8, (s >> 1) & 1);
        __syncthreads();

        const char* base = smem + DATA0 + (s & 1) * GU_STG;
        const __nv_bfloat16* Ah = (const __nv_bfloat16*)(base);
        const __nv_bfloat16* Al = (const __nv_bfloat16*)(base + GU_AB);
        const __nv_bfloat16* Bh = (const __nv_bfloat16*)(base + 2 * GU_AB + (mat ? 2 * GU_BB : 0));
        const __nv_bfloat16* Bl = (const __nv_bfloat16*)(base + 2 * GU_AB + (mat ? 3 * GU_BB : GU_BB));

        #pragma unroll
        for (int ks = 0; ks < 32; ks += 16) {
            FragA ah[4], al[4];
            #pragma unroll
            for (int m = 0; m < 4; m++) {
                wmma::load_matrix_sync(ah[m], Ah + (wm * 64 + m * 16) * 40 + ks, 40);
                wmma::load_matrix_sync(al[m], Al + (wm * 64 + m * 16) * 40 + ks, 40);
            }
            #pragma unroll
            for (int n = 0; n < 2; n++) {
                const int nc = wn * 32 + n * 16;
                FragB bh, bl;
                wmma::load_matrix_sync(bh, Bh + ks * 136 + nc, 136);
                wmma::load_matrix_sync(bl, Bl + ks * 136 + nc, 136);
                #pragma unroll
                for (int m = 0; m < 4; m++) {
                    wmma::mma_sync(c[m][n], ah[m], bh, c[m][n]);
                    wmma::mma_sync(c[m][n], ah[m], bl, c[m][n]);
                    wmma::mma_sync(c[m][n], al[m], bh, c[m][n]);
                }
            }
        }
        __syncthreads();
        if (s + 2 < NS) {
            GU_LOAD_A(s & 1, (s + 2) * 32); CPA_COMMIT();
            GU_LOAD_B(s & 1, (s + 2) * 32);
        }
    }

    // epilogue: two-pass (G then U) via fp32 stage [128][132]
    float* stg = (float*)(smem + DATA0);
    const int er = tid >> 2, ec0 = (tid & 3) * 32;

    if (mat == 0) {
        #pragma unroll
        for (int m = 0; m < 4; m++)
            #pragma unroll
            for (int n = 0; n < 2; n++)
                wmma::store_matrix_sync(stg + (wm * 64 + m * 16) * 132 + wn * 32 + n * 16,
                                        c[m][n], 132, wmma::mem_row_major);
    }
    __syncthreads();
    float gv[32];
    #pragma unroll
    for (int j = 0; j < 32; j++) gv[j] = stg[er * 132 + ec0 + j];
    __syncthreads();
    if (mat == 1) {
        #pragma unroll
        for (int m = 0; m < 4; m++)
            #pragma unroll
            for (int n = 0; n < 2; n++)
                wmma::store_matrix_sync(stg + (wm * 64 + m * 16) * 132 + wn * 32 + n * 16,
                                        c[m][n], 132, wmma::mem_row_major);
    }
    __syncthreads();
    {
        const size_t hrow = (size_t)e * 2048 + rb * 128 + er;
        __nv_bfloat16* hh = g_Hh + hrow * FF + (size_t)nb * 128 + ec0;
        __nv_bfloat16* hl = g_Hl + hrow * FF + (size_t)nb * 128 + ec0;
        unsigned short hv[32], lv[32];
        #pragma unroll
        for (int j = 0; j < 32; j++) {
            float g = gv[j];
            float u = stg[er * 132 + ec0 + j];
            float h = (g / (1.f + expf(-g))) * u;
            split1(h, hv[j], lv[j]);
        }
        #pragma unroll
        for (int q = 0; q < 4; q++) {
            *(uint4*)(hh + q * 8) = make_uint4(pk2(hv[q*8+0],hv[q*8+1]), pk2(hv[q*8+2],hv[q*8+3]),
                                               pk2(hv[q*8+4],hv[q*8+5]), pk2(hv[q*8+6],hv[q*8+7]));
            *(uint4*)(hl + q * 8) = make_uint4(pk2(lv[q*8+0],lv[q*8+1]), pk2(lv[q*8+2],lv[q*8+3]),
                                               pk2(lv[q*8+4],lv[q*8+5]), pk2(lv[q*8+6],lv[q*8+7]));
        }
    }
    #undef GU_LOAD_A
    #undef GU_LOAD_B
}

// ================= GEMM2: down-proj (bf16x3 HMMA) + gated atomic accumulate =================
// BM=128, BN=256, BK=32, 512 threads = 16 warps: 2m x 8n, warp 64x32.
__global__ __launch_bounds__(512, 1) void gemm_down(float* __restrict__ out)
{
    const int e  = blockIdx.x >> 4;
    const int rb = blockIdx.x & 15;
    const int ne = g_cnt[e];
    if (rb * 128 >= ne) return;
    const int nb = blockIdx.y;

    extern __shared__ char smem[];
    const uint32_t sb = smem_u32(smem);
    const int tid  = threadIdx.x;
    const int warp = tid >> 5;
    const int wm   = warp >> 3;       // 0..1
    const int wn   = warp & 7;        // 0..7

    if (tid == 0) {
        MBARRIER_INIT(sb + 0, 64);
        MBARRIER_INIT(sb + 8, 64);
        FENCE_ASYNC_SHARED();
    }
    __syncthreads();

    // A loader: H rows
    const int arow = tid >> 2, achk = (tid & 3) * 8;
    const size_t hrow = (size_t)e * 2048 + rb * 128 + arow;
    const __nv_bfloat16* sAh = g_Hh + hrow * FF + achk;
    const __nv_bfloat16* sAl = g_Hl + hrow * FF + achk;
    const uint32_t dA = sb + DATA0 + (uint32_t)arow * 80 + achk * 2;

    // B bulk loader: threads 0..63, plane = tid>>5 (Wdh, Wdl), row = tid&31, 512B rows
    const __nv_bfloat16* bsrc = nullptr;
    uint32_t bdst = 0;
    if (tid < 64) {
        const int plane = tid >> 5, row = tid & 31;
        const __nv_bfloat16* pb = plane ? g_Wd_lo : g_Wd_hi;
        bsrc = pb + (size_t)e * FF * DD + (size_t)row * DD + (size_t)nb * 256;
        bdst = sb + DATA0 + 2 * DN_AB + plane * DN_BB + row * 528;
    }

    #define DN_LOAD_A(st, k) do { \
        uint32_t o = (uint32_t)(st) * DN_STG; \
        cpa16(dA + o,         sAh + (k)); \
        cpa16(dA + o + DN_AB, sAl + (k)); \
    } while (0)
    #define DN_LOAD_B(st, k) do { \
        if (tid < 64) bulk_cp(sb + (st) * 8, bdst + (uint32_t)(st) * DN_STG, bsrc + (size_t)(k) * DD, 512); \
    } while (0)

    FragC c[4][2];
    #pragma unroll
    for (int m = 0; m < 4; m++)
        #pragma unroll
        for (int n = 0; n < 2; n++) wmma::fill_fragment(c[m][n], 0.f);

    DN_LOAD_A(0, 0);  CPA_COMMIT();
    DN_LOAD_A(1, 32); CPA_COMMIT();
    DN_LOAD_B(0, 0);
    DN_LOAD_B(1, 32);

    const int NS = FF / 32;   // 256
    #pragma unroll 1
    for (int s = 0; s < NS; s++) {
        if (s + 1 < NS) CPA_WAIT1(); else CPA_WAIT0();
        mbar_wait_parity(sb + (s & 1) * 8, (s >> 1) & 1);
        __syncthreads();

        const char* base = smem + DATA0 + (s & 1) * DN_STG;
        const __nv_bfloat16* Ah = (const __nv_bfloat16*)(base);
        const __nv_bfloat16* Al = (const __nv_bfloat16*)(base + DN_AB);
        const __nv_bfloat16* Bh = (const __nv_bfloat16*)(base + 2 * DN_AB);
        const __nv_bfloat16* Bl = (const __nv_bfloat16*)(base + 2 * DN_AB + DN_BB);

        #pragma unroll
        for (int ks = 0; ks < 32; ks += 16) {
            FragA ah[4], al[4];
            #pragma unroll
            for (int m = 0; m < 4; m++) {
                wmma::load_matrix_sync(ah[m], Ah + (wm * 64 + m * 16) * 40 + ks, 40);
                wmma::load_matrix_sync(al[m], Al + (wm * 64 + m * 16) * 40 + ks, 40);
            }
            #pragma unroll
            for (int n = 0; n < 2; n++) {
                const int nc = wn * 32 + n * 16;
                FragB bh, bl;
                wmma::load_matrix_sync(bh, Bh + ks * 264 + nc, 264);
                wmma::load_matrix_sync(bl, Bl + ks * 264 + nc, 264);
                #pragma unroll
                for (int m = 0; m < 4; m++) {
                    wmma::mma_sync(c[m][n], ah[m], bh, c[m][n]);
                    wmma::mma_sync(c[m][n], ah[m], bl, c[m][n]);
                    wmma::mma_sync(c[m][n], al[m], bh, c[m][n]);
                }
            }
        }
        __syncthreads();
        if (s + 2 < NS) {
            DN_LOAD_A(s & 1, (s + 2) * 32); CPA_COMMIT();
            DN_LOAD_B(s & 1, (s + 2) * 32);
        }
    }

    // epilogue: two N-halves via fp32 stage [128][132]; gated atomic adds
    float* stg = (float*)(smem + DATA0);
    const int er = tid >> 2, ec0 = (tid & 3) * 32;
    const int grow = rb * 128 + er;
    const bool live = (grow < ne);
    const int   tok = live ? g_tok[e][grow] : 0;
    const float gvv = live ? g_gate[e][grow] : 0.f;

    #pragma unroll
    for (int half = 0; half < 2; half++) {
        if ((wn >> 2) == half) {
            const int wnh = wn & 3;
            #pragma unroll
            for (int m = 0; m < 4; m++)
                #pragma unroll
                for (int n = 0; n < 2; n++)
                    wmma::store_matrix_sync(stg + (wm * 64 + m * 16) * 132 + wnh * 32 + n * 16,
                                            c[m][n], 132, wmma::mem_row_major);
        }
        __syncthreads();
        if (live) {
            float* orow = out + (size_t)tok * DD + (size_t)nb * 256 + half * 128 + ec0;
            #pragma unroll
            for (int j = 0; j < 32; j++)
                atomicAdd(&orow[j], gvv * stg[er * 132 + ec0 + j]);
        }
        __syncthreads();
    }
    #undef DN_LOAD_A
    #undef DN_LOAD_B
}

// ---------------- launch ----------------
extern "C" void kernel_launch(void* const* d_in, const int* in_sizes, int n_in,
                              void* d_out, int out_size) {
    const float* x  = (const float*)d_in[0];
    const float* Wr = (const float*)d_in[1];
    const float* Wg = (const float*)d_in[2];
    const float* Wu = (const float*)d_in[3];
    const float* Wd = (const float*)d_in[4];
    float* out = (float*)d_out;

    static int attr_done = 0;
    if (!attr_done) {
        cudaFuncSetAttribute(gemm_gateup, cudaFuncAttributeMaxDynamicSharedMemorySize, GU_SMEM);
        cudaFuncSetAttribute(gemm_down,   cudaFuncAttributeMaxDynamicSharedMemorySize, DN_SMEM);
        attr_done = 1;
    }

    const int n_out = NT * DD;
    init_kernel<<<(n_out + 255) / 256, 256>>>(out, n_out);

    // pre-split weights + x into bf16 hi/lo planes
    {
        __nv_bfloat16 *wg_h, *wg_l, *wu_h, *wu_l, *wd_h, *wd_l, *x_h, *x_l;
        cudaGetSymbolAddress((void**)&wg_h, g_Wg_hi); cudaGetSymbolAddress((void**)&wg_l, g_Wg_lo);
        cudaGetSymbolAddress((void**)&wu_h, g_Wu_hi); cudaGetSymbolAddress((void**)&wu_l, g_Wu_lo);
        cudaGetSymbolAddress((void**)&wd_h, g_Wd_hi); cudaGetSymbolAddress((void**)&wd_l, g_Wd_lo);
        cudaGetSymbolAddress((void**)&x_h,  g_x_hi);  cudaGetSymbolAddress((void**)&x_l,  g_x_lo);
        size_t w4 = WSZ / 4;
        split_kernel<<<(unsigned)((w4 + 255) / 256), 256>>>(Wg, wg_h, wg_l, w4);
        split_kernel<<<(unsigned)((w4 + 255) / 256), 256>>>(Wu, wu_h, wu_l, w4);
        split_kernel<<<(unsigned)((w4 + 255) / 256), 256>>>(Wd, wd_h, wd_l, w4);
        size_t x4 = (size_t)NT * DD / 4;
        split_kernel<<<(unsigned)((x4 + 255) / 256), 256>>>(x, x_h, x_l, x4);
    }

    router_kernel<<<(NT * 32 + 127) / 128, 128>>>(x, Wr);

    // all experts in one launch each
    gemm_gateup<<<dim3(EE * 16, FF / 128), 512, GU_SMEM>>>();
    gemm_down  <<<dim3(EE * 16, DD / 256), 512, DN_SMEM>>>(out);
}

// round 17
// speedup vs baseline: 3.9538x; 3.9538x over previous
#include <cuda_runtime.h>
#include <cuda_fp16.h>
#include <mma.h>
#include <math.h>
#include <cstdint>

using namespace nvcuda;

// Problem constants
#define BB 2
#define SS 1024
#define DD 2048
#define FF 8192
#define EE 4
#define NT (BB*SS)            // 2048 tokens
#define WSZ ((size_t)EE*DD*FF)
#define HROWS ((size_t)EE*2048)

// ---------------- device scratch (no allocations allowed) ----------------
__device__ int   g_cnt[EE];
__device__ int   g_tok[EE][NT];
__device__ float g_gate[EE][NT];
// fp16 copies (single plane)
__device__ half g_Wg_h[WSZ];
__device__ half g_Wu_h[WSZ];
__device__ half g_Wd_h[WSZ];
__device__ half g_x_h[(size_t)NT*DD];
__device__ half g_H[HROWS*FF];

// ---------------- helpers ----------------
__device__ __forceinline__ uint32_t smem_u32(const void* p) {
    uint32_t a;
    asm("{ .reg .u64 t; cvta.to.shared.u64 t, %1; cvt.u32.u64 %0, t; }" : "=r"(a) : "l"(p));
    return a;
}
__device__ __forceinline__ void cpa16(uint32_t dst, const void* src) {
    asm volatile("{ .reg .u64 g; cvta.to.global.u64 g, %1; cp.async.cg.shared.global [%0], [g], 16; }"
                 :: "r"(dst), "l"(src) : "memory");
}
#define CPA_COMMIT() asm volatile("cp.async.commit_group;" ::: "memory")
#define CPA_WAIT1()  asm volatile("cp.async.wait_group 1;" ::: "memory")
#define CPA_WAIT0()  asm volatile("cp.async.wait_group 0;" ::: "memory")

// ---------------- init / convert / router ----------------
__global__ void init_kernel(float* __restrict__ out, int n) {
    int i = blockIdx.x * blockDim.x + threadIdx.x;
    if (i < n) out[i] = 0.0f;
    if (i < EE) g_cnt[i] = 0;
}

__global__ void cvt_kernel(const float* __restrict__ src, half* __restrict__ dst, size_t n4) {
    size_t i = (size_t)blockIdx.x * blockDim.x + threadIdx.x;
    if (i >= n4) return;
    float4 v = *(const float4*)(src + i * 4);
    half2 a = __floats2half2_rn(v.x, v.y);
    half2 b = __floats2half2_rn(v.z, v.w);
    *(uint2*)(dst + i * 4) = make_uint2(*(uint32_t*)&a, *(uint32_t*)&b);
}

__global__ void router_kernel(const float* __restrict__ x, const float* __restrict__ Wr) {
    int gwarp = (blockIdx.x * blockDim.x + threadIdx.x) >> 5;
    int lane  = threadIdx.x & 31;
    if (gwarp >= NT) return;
    const float* xr = x + (size_t)gwarp * DD;
    float a0 = 0.f, a1 = 0.f, a2 = 0.f, a3 = 0.f;
    for (int d = lane; d < DD; d += 32) {
        float xv = xr[d];
        float4 w = *(const float4*)(Wr + (size_t)d * 4);
        a0 += xv * w.x; a1 += xv * w.y; a2 += xv * w.z; a3 += xv * w.w;
    }
    #pragma unroll
    for (int off = 16; off; off >>= 1) {
        a0 += __shfl_down_sync(0xffffffffu, a0, off);
        a1 += __shfl_down_sync(0xffffffffu, a1, off);
        a2 += __shfl_down_sync(0xffffffffu, a2, off);
        a3 += __shfl_down_sync(0xffffffffu, a3, off);
    }
    if (lane == 0) {
        float l[4] = {a0, a1, a2, a3};
        float m = fmaxf(fmaxf(l[0], l[1]), fmaxf(l[2], l[3]));
        float p[4], s = 0.f;
        #pragma unroll
        for (int e = 0; e < 4; e++) { p[e] = expf(l[e] - m); s += p[e]; }
        int i0 = 0; float b0 = p[0];
        #pragma unroll
        for (int e = 1; e < 4; e++) if (p[e] > b0) { b0 = p[e]; i0 = e; }
        int i1 = -1; float b1 = -1.f;
        #pragma unroll
        for (int e = 0; e < 4; e++) if (e != i0 && p[e] > b1) { b1 = p[e]; i1 = e; }
        float inv = 1.f / s;
        int pos0 = atomicAdd(&g_cnt[i0], 1);
        g_tok[i0][pos0] = gwarp; g_gate[i0][pos0] = b0 * inv;
        int pos1 = atomicAdd(&g_cnt[i1], 1);
        g_tok[i1][pos1] = gwarp; g_gate[i1][pos1] = b1 * inv;
    }
}

// ================= smem layout =================
// gateup stage: A [128][40] half (10240B) + BG [32][136] (8704B) + BU [32][136] (8704B)
#define GU_AB   10240
#define GU_BB   8704
#define GU_STG  (GU_AB + 2*GU_BB)      // 27648
#define GU_SMEM (3*GU_STG)             // 82944  (epilogue stage 128*132*4=67584 fits)
// down stage: A [128][40] half + B [32][264] half (16896B)
#define DN_AB   10240
#define DN_BB   16896
#define DN_STG  (DN_AB + DN_BB)        // 27136
#define DN_SMEM (3*DN_STG)             // 81408

typedef wmma::fragment<wmma::matrix_a, 16, 16, 16, half, wmma::row_major> FragA;
typedef wmma::fragment<wmma::matrix_b, 16, 16, 16, half, wmma::row_major> FragB;
typedef wmma::fragment<wmma::accumulator, 16, 16, 16, float> FragC;

// ================= GEMM1: gate+up (fp16 HMMA) + SiLU*mul -> H fp16 =================
// BM=128, BN=128 (G) + 128 (U), BK=32, 512 threads = 16 warps: 2m x 2mat x 4n, warp 64x32.
__global__ __launch_bounds__(512, 1) void gemm_gateup()
{
    const int e  = blockIdx.x >> 4;
    const int rb = blockIdx.x & 15;
    const int ne = g_cnt[e];
    if (rb * 128 >= ne) return;
    const int nb = blockIdx.y;

    extern __shared__ char smem[];
    const uint32_t sb = smem_u32(smem);
    const int tid  = threadIdx.x;
    const int warp = tid >> 5;
    const int wm   = warp >> 3;
    const int mat  = (warp >> 2) & 1;
    const int wn   = warp & 3;

    // A loader: 128 rows x 4 chunks(8 halfs) = 512 slots, 1 op/thread
    const int arow = tid >> 2, achk = (tid & 3) * 8;
    const int tok  = g_tok[e][min(rb * 128 + arow, ne - 1)];
    const half* sA = g_x_h + (size_t)tok * DD + achk;
    const uint32_t dA = sb + (uint32_t)arow * 80 + achk * 2;

    // B loader: 32 rows x 16 chunks = 512 slots; 2 planes (G,U) = 2 ops/thread
    const int brow = tid >> 4, bchk = (tid & 15) * 8;
    const size_t wb = (size_t)e * DD * FF + (size_t)brow * FF + (size_t)nb * 128 + bchk;
    const half* sG = g_Wg_h + wb;
    const half* sU = g_Wu_h + wb;
    const uint32_t dB = sb + GU_AB + (uint32_t)brow * 272 + bchk * 2;

    #define GU_LOAD(st, k) do { \
        uint32_t o = (uint32_t)(st) * GU_STG; size_t kf = (size_t)(k) * FF; \
        cpa16(dA + o,          sA + (k)); \
        cpa16(dB + o,          sG + kf); \
        cpa16(dB + o + GU_BB,  sU + kf); \
    } while (0)

    FragC c[4][2];
    #pragma unroll
    for (int m = 0; m < 4; m++)
        #pragma unroll
        for (int n = 0; n < 2; n++) wmma::fill_fragment(c[m][n], 0.f);

    GU_LOAD(0, 0);  CPA_COMMIT();
    GU_LOAD(1, 32); CPA_COMMIT();

    const int NS = DD / 32;   // 64
    int buf = 0;
    #pragma unroll 1
    for (int s = 0; s < NS; s++) {
        if (s + 1 < NS) CPA_WAIT1(); else CPA_WAIT0();
        __syncthreads();

        const char* base = smem + buf * GU_STG;
        const half* A  = (const half*)(base);
        const half* Bm = (const half*)(base + GU_AB + (mat ? GU_BB : 0));

        #pragma unroll
        for (int ks = 0; ks < 32; ks += 16) {
            FragA a[4];
            #pragma unroll
            for (int m = 0; m < 4; m++)
                wmma::load_matrix_sync(a[m], A + (wm * 64 + m * 16) * 40 + ks, 40);
            #pragma unroll
            for (int n = 0; n < 2; n++) {
                FragB b;
                wmma::load_matrix_sync(b, Bm + ks * 136 + wn * 32 + n * 16, 136);
                #pragma unroll
                for (int m = 0; m < 4; m++)
                    wmma::mma_sync(c[m][n], a[m], b, c[m][n]);
            }
        }
        // issue next stage into buffer (s+2)%3 — all warps are past the sync,
        // so nobody still reads that buffer (it held stage s-1).
        if (s + 2 < NS) {
            int nbuf = buf + 2; if (nbuf >= 3) nbuf -= 3;
            GU_LOAD(nbuf, (s + 2) * 32); CPA_COMMIT();
        }
        if (++buf == 3) buf = 0;
    }

    // epilogue: two-pass (G then U) via fp32 stage [128][132]
    __syncthreads();
    float* stg = (float*)smem;
    const int er = tid >> 2, ec0 = (tid & 3) * 32;

    if (mat == 0) {
        #pragma unroll
        for (int m = 0; m < 4; m++)
            #pragma unroll
            for (int n = 0; n < 2; n++)
                wmma::store_matrix_sync(stg + (wm * 64 + m * 16) * 132 + wn * 32 + n * 16,
                                        c[m][n], 132, wmma::mem_row_major);
    }
    __syncthreads();
    float gv[32];
    #pragma unroll
    for (int j = 0; j < 32; j++) gv[j] = stg[er * 132 + ec0 + j];
    __syncthreads();
    if (mat == 1) {
        #pragma unroll
        for (int m = 0; m < 4; m++)
            #pragma unroll
            for (int n = 0; n < 2; n++)
                wmma::store_matrix_sync(stg + (wm * 64 + m * 16) * 132 + wn * 32 + n * 16,
                                        c[m][n], 132, wmma::mem_row_major);
    }
    __syncthreads();
    {
        const size_t hrow = (size_t)e * 2048 + rb * 128 + er;
        half* hp = g_H + hrow * FF + (size_t)nb * 128 + ec0;
        uint32_t pk[16];
        #pragma unroll
        for (int j = 0; j < 16; j++) {
            float g0 = gv[2*j],     u0 = stg[er * 132 + ec0 + 2*j];
            float g1 = gv[2*j + 1], u1 = stg[er * 132 + ec0 + 2*j + 1];
            float h0 = (g0 / (1.f + expf(-g0))) * u0;
            float h1 = (g1 / (1.f + expf(-g1))) * u1;
            half2 hh = __floats2half2_rn(h0, h1);
            pk[j] = *(uint32_t*)&hh;
        }
        #pragma unroll
        for (int q = 0; q < 4; q++)
            *(uint4*)(hp + q * 8) = make_uint4(pk[q*4+0], pk[q*4+1], pk[q*4+2], pk[q*4+3]);
    }
    #undef GU_LOAD
}

// ================= GEMM2: down-proj (fp16 HMMA) + gated atomic accumulate =================
// BM=128, BN=256, BK=32, 512 threads = 16 warps: 2m x 8n, warp 64x32.
__global__ __launch_bounds__(512, 1) void gemm_down(float* __restrict__ out)
{
    const int e  = blockIdx.x >> 4;
    const int rb = blockIdx.x & 15;
    const int ne = g_cnt[e];
    if (rb * 128 >= ne) return;
    const int nb = blockIdx.y;

    extern __shared__ char smem[];
    const uint32_t sb = smem_u32(smem);
    const int tid  = threadIdx.x;
    const int warp = tid >> 5;
    const int wm   = warp >> 3;       // 0..1
    const int wn   = warp & 7;        // 0..7

    // A loader: H rows, 1 op/thread
    const int arow = tid >> 2, achk = (tid & 3) * 8;
    const size_t hrow = (size_t)e * 2048 + rb * 128 + arow;
    const half* sA = g_H + hrow * FF + achk;
    const uint32_t dA = sb + (uint32_t)arow * 80 + achk * 2;

    // B loader: 32 rows x 256 halfs; 16 thr/row x 16 halfs -> 2 ops/thread
    const int brow = tid >> 4, bchk = (tid & 15) * 16;
    const half* sB = g_Wd_h + (size_t)e * FF * DD + (size_t)brow * DD + (size_t)nb * 256 + bchk;
    const uint32_t dB = sb + DN_AB + (uint32_t)brow * 528 + bchk * 2;

    #define DN_LOAD(st, k) do { \
        uint32_t o = (uint32_t)(st) * DN_STG; size_t kf = (size_t)(k) * DD; \
        cpa16(dA + o,       sA + (k)); \
        cpa16(dB + o,       sB + kf); \
        cpa16(dB + o + 16,  sB + kf + 8); \
    } while (0)

    FragC c[4][2];
    #pragma unroll
    for (int m = 0; m < 4; m++)
        #pragma unroll
        for (int n = 0; n < 2; n++) wmma::fill_fragment(c[m][n], 0.f);

    DN_LOAD(0, 0);  CPA_COMMIT();
    DN_LOAD(1, 32); CPA_COMMIT();

    const int NS = FF / 32;   // 256
    int buf = 0;
    #pragma unroll 1
    for (int s = 0; s < NS; s++) {
        if (s + 1 < NS) CPA_WAIT1(); else CPA_WAIT0();
        __syncthreads();

        const char* base = smem + buf * DN_STG;
        const half* A = (const half*)(base);
        const half* B = (const half*)(base + DN_AB);

        #pragma unroll
        for (int ks = 0; ks < 32; ks += 16) {
            FragA a[4];
            #pragma unroll
            for (int m = 0; m < 4; m++)
                wmma::load_matrix_sync(a[m], A + (wm * 64 + m * 16) * 40 + ks, 40);
            #pragma unroll
            for (int n = 0; n < 2; n++) {
                FragB b;
                wmma::load_matrix_sync(b, B + ks * 264 + wn * 32 + n * 16, 264);
                #pragma unroll
                for (int m = 0; m < 4; m++)
                    wmma::mma_sync(c[m][n], a[m], b, c[m][n]);
            }
        }
        if (s + 2 < NS) {
            int nbuf = buf + 2; if (nbuf >= 3) nbuf -= 3;
            DN_LOAD(nbuf, (s + 2) * 32); CPA_COMMIT();
        }
        if (++buf == 3) buf = 0;
    }

    // epilogue: two N-halves via fp32 stage [128][132]; gated atomic adds
    __syncthreads();
    float* stg = (float*)smem;
    const int er = tid >> 2, ec0 = (tid & 3) * 32;
    const int grow = rb * 128 + er;
    const bool live = (grow < ne);
    const int   tok = live ? g_tok[e][grow] : 0;
    const float gvv = live ? g_gate[e][grow] : 0.f;

    #pragma unroll
    for (int half_i = 0; half_i < 2; half_i++) {
        if ((wn >> 2) == half_i) {
            const int wnh = wn & 3;
            #pragma unroll
            for (int m = 0; m < 4; m++)
                #pragma unroll
                for (int n = 0; n < 2; n++)
                    wmma::store_matrix_sync(stg + (wm * 64 + m * 16) * 132 + wnh * 32 + n * 16,
                                            c[m][n], 132, wmma::mem_row_major);
        }
        __syncthreads();
        if (live) {
            float* orow = out + (size_t)tok * DD + (size_t)nb * 256 + half_i * 128 + ec0;
            #pragma unroll
            for (int j = 0; j < 32; j++)
                atomicAdd(&orow[j], gvv * stg[er * 132 + ec0 + j]);
        }
        __syncthreads();
    }
    #undef DN_LOAD
}

// ---------------- launch ----------------
extern "C" void kernel_launch(void* const* d_in, const int* in_sizes, int n_in,
                              void* d_out, int out_size) {
    const float* x  = (const float*)d_in[0];
    const float* Wr = (const float*)d_in[1];
    const float* Wg = (const float*)d_in[2];
    const float* Wu = (const float*)d_in[3];
    const float* Wd = (const float*)d_in[4];
    float* out = (float*)d_out;

    static int attr_done = 0;
    if (!attr_done) {
        cudaFuncSetAttribute(gemm_gateup, cudaFuncAttributeMaxDynamicSharedMemorySize, GU_SMEM);
        cudaFuncSetAttribute(gemm_down,   cudaFuncAttributeMaxDynamicSharedMemorySize, DN_SMEM);
        attr_done = 1;
    }

    const int n_out = NT * DD;
    init_kernel<<<(n_out + 255) / 256, 256>>>(out, n_out);

    // convert weights + x to fp16
    {
        half *wg, *wu, *wd, *xh;
        cudaGetSymbolAddress((void**)&wg, g_Wg_h);
        cudaGetSymbolAddress((void**)&wu, g_Wu_h);
        cudaGetSymbolAddress((void**)&wd, g_Wd_h);
        cudaGetSymbolAddress((void**)&xh, g_x_h);
        size_t w4 = WSZ / 4;
        cvt_kernel<<<(unsigned)((w4 + 255) / 256), 256>>>(Wg, wg, w4);
        cvt_kernel<<<(unsigned)((w4 + 255) / 256), 256>>>(Wu, wu, w4);
        cvt_kernel<<<(unsigned)((w4 + 255) / 256), 256>>>(Wd, wd, w4);
        size_t x4 = (size_t)NT * DD / 4;
        cvt_kernel<<<(unsigned)((x4 + 255) / 256), 256>>>(x, xh, x4);
    }

    router_kernel<<<(NT * 32 + 127) / 128, 128>>>(x, Wr);

    gemm_gateup<<<dim3(EE * 16, FF / 128), 512, GU_SMEM>>>();
    gemm_down  <<<dim3(EE * 16, DD / 256), 512, DN_SMEM>>>(out);
}